// round 5
// baseline (speedup 1.0000x reference)
#include <cuda_runtime.h>
#include <cstdint>

// Problem constants
#define T_SEQ 200
#define BATCH 1024
#define EMB   128
#define HID   128
#define G3    384          // 3*HID, gate order r,z,n
#define NROWS (BATCH * T_SEQ)

// 314 MB scratch for gx = x @ W_ih^T + b_ih  (static __device__: allocation-free)
__device__ float g_gx[(size_t)NROWS * G3];

// Packed fp32x2 FMA: d.lo += a.lo*b.lo ; d.hi += a.hi*b.hi
__device__ __forceinline__ void fma2(unsigned long long& d,
                                     unsigned long long a,
                                     unsigned long long b) {
    asm("fma.rn.f32x2 %0, %1, %2, %0;" : "+l"(d) : "l"(a), "l"(b));
}
__device__ __forceinline__ float pairsum(unsigned long long d) {
    float lo = __uint_as_float((unsigned)(d & 0xffffffffULL));
    float hi = __uint_as_float((unsigned)(d >> 32));
    return lo + hi;
}

// ---------------------------------------------------------------------------
// Kernel 1: fused embedding gather + input-side GEMM (R2 version: best known)
// ---------------------------------------------------------------------------
#define RM    64
#define XPAD  132          // 33 float4s per row: odd pitch -> conflict-free
#define SM1_BYTES ((RM * XPAD + 128 * XPAD) * 4)

__global__ __launch_bounds__(256) void gx_kernel(
    const int*   __restrict__ seq,
    const float* __restrict__ emb,
    const float* __restrict__ Wih,
    const float* __restrict__ bih)
{
    extern __shared__ float sm[];
    float* xs = sm;                  // [RM][XPAD]   x tile, k-major
    float* ws = sm + RM * XPAD;      // [128][XPAD]  W tile, k-major

    const int t    = threadIdx.x;
    const int row0 = blockIdx.x * RM;
    const int c0   = blockIdx.y * 128;

    {
        int r  = t >> 2;
        int k0 = (t & 3) * 32;
        int idx = __ldg(seq + row0 + r);
        const float4* src = (const float4*)(emb + (size_t)idx * EMB + k0);
        float4* dst = (float4*)(xs + r * XPAD + k0);
        #pragma unroll
        for (int i = 0; i < 8; i++) dst[i] = src[i];
    }
    {
        #pragma unroll
        for (int i = 0; i < 16; i++) {
            int flat = t + 256 * i;
            int c  = flat >> 5;
            int k4 = (flat & 31) << 2;
            *(float4*)(ws + c * XPAD + k4) =
                *(const float4*)(Wih + (size_t)(c0 + c) * EMB + k4);
        }
    }
    __syncthreads();

    const int rg = t >> 5;
    const int cg = t & 31;
    unsigned long long acc[8][4];
    #pragma unroll
    for (int r = 0; r < 8; r++)
        #pragma unroll
        for (int j = 0; j < 4; j++) acc[r][j] = 0ULL;

    const float* xbase = xs + (rg * 8) * XPAD;

    #pragma unroll 4
    for (int k = 0; k < 128; k += 4) {
        ulonglong2 wv[4];
        #pragma unroll
        for (int j = 0; j < 4; j++)
            wv[j] = *(const ulonglong2*)(ws + (cg + 32 * j) * XPAD + k);
        #pragma unroll
        for (int r = 0; r < 8; r++) {
            ulonglong2 xv = *(const ulonglong2*)(xbase + r * XPAD + k);
            #pragma unroll
            for (int j = 0; j < 4; j++) {
                fma2(acc[r][j], xv.x, wv[j].x);
                fma2(acc[r][j], xv.y, wv[j].y);
            }
        }
    }

    #pragma unroll
    for (int j = 0; j < 4; j++) {
        int c = c0 + cg + 32 * j;
        float bv = __ldg(bih + c);
        #pragma unroll
        for (int r = 0; r < 8; r++) {
            int row = row0 + rg * 8 + r;
            g_gx[(size_t)row * G3 + c] = pairsum(acc[r][j]) + bv;
        }
    }
}

// ---------------------------------------------------------------------------
// Kernel 2: GRU recurrence, 768 threads/CTA, thread = (gate, k-half).
// Each thread: 8 independent f32x2 accumulator chains (one per batch row),
// 16 private W LDS.128 + 128 broadcast h LDS.128 per step, one shfl.bfly
// to combine k-halves. 24 warps/CTA = 6/SMSP hides all latencies;
// per-SMSP fma2 floor = 3072 cyc/step.
// ---------------------------------------------------------------------------
#define BM     8
#define NTHR2  768
#define KPAD   132
#define GHPAD  388
#define SM2_BYTES ((G3 * KPAD + BM * KPAD + BM * GHPAD) * 4)

__device__ __forceinline__ float fsigmoid(float x) {
    return __fdividef(1.f, 1.f + __expf(-x));
}

__global__ __launch_bounds__(NTHR2, 1) void gru_kernel(
    const float* __restrict__ Whh,
    const float* __restrict__ bhh,
    float*       __restrict__ out)
{
    extern __shared__ float sm[];
    float* ws  = sm;                          // [G3][KPAD]  W_hh, k-contiguous
    float* hs  = ws + G3 * KPAD;              // [BM][KPAD]  hidden state
    float* ghs = hs + BM * KPAD;              // [BM][GHPAD] gh scratch

    const int t  = threadIdx.x;
    const int b0 = blockIdx.x * BM;

    const int gate  = t >> 1;                 // 0..383
    const int khalf = t & 1;                  // 0..1
    const int k0    = khalf * 64;

    // ---- load W_hh into SMEM (12288 float4s, 16 per thread) ----
    #pragma unroll
    for (int i = 0; i < 16; i++) {
        int flat = t + NTHR2 * i;
        int g  = flat >> 5;
        int k4 = (flat & 31) << 2;
        *(float4*)(ws + g * KPAD + k4) = *(const float4*)(Whh + (size_t)g * HID + k4);
    }
    const float bias = __ldg(bhh + gate);
    const unsigned long long binit =
        khalf ? 0ULL : (unsigned long long)__float_as_uint(bias);

    // ---- h = 0 ----
    for (int pos = t; pos < BM * 128; pos += NTHR2)
        hs[(pos >> 7) * KPAD + (pos & 127)] = 0.f;
    __syncthreads();

    const float* wp = ws + gate * KPAD + k0;

    // phase-2 mapping: p0 = t (rows 0..5), p1 = t + 768 (t<256 -> rows 6..7)
    const int r0 = t >> 7;                    // 0..5
    const int kk = t & 127;
    const bool has2 = (t < 256);
    const int r1 = 6 + (t >> 7 > 5 ? 0 : (t >> 7));  // placeholder, fixed below
    const int r1f = 6 + (t >> 7);             // valid only when t<256 -> 6 or 7

    for (int ts = 0; ts < T_SEQ; ts++) {
        // ---- prefetch this step's gx (hidden under GEMM) ----
        float xr0, xz0, xn0, xr1, xz1, xn1;
        {
            const float* gp = g_gx + ((size_t)(b0 + r0) * T_SEQ + ts) * G3 + kk;
            xr0 = __ldg(gp); xz0 = __ldg(gp + 128); xn0 = __ldg(gp + 256);
        }
        if (has2) {
            const float* gp = g_gx + ((size_t)(b0 + r1f) * T_SEQ + ts) * G3 + kk;
            xr1 = __ldg(gp); xz1 = __ldg(gp + 128); xn1 = __ldg(gp + 256);
        }

        // ---- phase 1: gh[gate, r] over this thread's k-half ----
        unsigned long long acc[BM];
        #pragma unroll
        for (int r = 0; r < BM; r++) acc[r] = binit;

        #pragma unroll
        for (int j = 0; j < 16; j++) {
            ulonglong2 wv = *(const ulonglong2*)(wp + 4 * j);
            #pragma unroll
            for (int r = 0; r < BM; r++) {
                ulonglong2 hv = *(const ulonglong2*)(hs + r * KPAD + k0 + 4 * j);
                fma2(acc[r], hv.x, wv.x);
                fma2(acc[r], hv.y, wv.y);
            }
        }
        #pragma unroll
        for (int r = 0; r < BM; r++) {
            float s = pairsum(acc[r]);
            s += __shfl_xor_sync(0xffffffffu, s, 1);
            if (!khalf) ghs[r * GHPAD + gate] = s;
        }
        __syncthreads();

        // ---- phase 2: gates + hidden update ----
        {
            float hrv = ghs[r0 * GHPAD + kk];
            float hzv = ghs[r0 * GHPAD + 128 + kk];
            float hnv = ghs[r0 * GHPAD + 256 + kk];
            float hprev = hs[r0 * KPAD + kk];
            float rr = fsigmoid(xr0 + hrv);
            float zz = fsigmoid(xz0 + hzv);
            float nn = 2.f * fsigmoid(2.f * (xn0 + rr * hnv)) - 1.f;  // tanh
            hs[r0 * KPAD + kk] = (1.f - zz) * nn + zz * hprev;
        }
        if (has2) {
            float hrv = ghs[r1f * GHPAD + kk];
            float hzv = ghs[r1f * GHPAD + 128 + kk];
            float hnv = ghs[r1f * GHPAD + 256 + kk];
            float hprev = hs[r1f * KPAD + kk];
            float rr = fsigmoid(xr1 + hrv);
            float zz = fsigmoid(xz1 + hzv);
            float nn = 2.f * fsigmoid(2.f * (xn1 + rr * hnv)) - 1.f;  // tanh
            hs[r1f * KPAD + kk] = (1.f - zz) * nn + zz * hprev;
        }
        __syncthreads();
    }

    // ---- write final hidden state ----
    out[(size_t)(b0 + r0) * HID + kk] = hs[r0 * KPAD + kk];
    if (has2)
        out[(size_t)(b0 + r1f) * HID + kk] = hs[r1f * KPAD + kk];
}

// ---------------------------------------------------------------------------
// Launch
// ---------------------------------------------------------------------------
extern "C" void kernel_launch(void* const* d_in, const int* in_sizes, int n_in,
                              void* d_out, int out_size)
{
    const int*   seq = (const int*)  d_in[0];  // [1024, 200] int32
    const float* emb = (const float*)d_in[1];  // [100000, 128]
    const float* Wih = (const float*)d_in[2];  // [384, 128]
    const float* Whh = (const float*)d_in[3];  // [384, 128]
    const float* bih = (const float*)d_in[4];  // [384]
    const float* bhh = (const float*)d_in[5];  // [384]
    float* out = (float*)d_out;                // [1024, 128]

    cudaFuncSetAttribute(gx_kernel,  cudaFuncAttributeMaxDynamicSharedMemorySize, SM1_BYTES);
    cudaFuncSetAttribute(gru_kernel, cudaFuncAttributeMaxDynamicSharedMemorySize, SM2_BYTES);

    dim3 grid1(NROWS / RM, G3 / 128);          // 3200 x 3
    gx_kernel<<<grid1, 256, SM1_BYTES>>>(seq, emb, Wih, bih);

    gru_kernel<<<BATCH / BM, NTHR2, SM2_BYTES>>>(Whh, bhh, out);
}

// round 6
// speedup vs baseline: 2.2370x; 2.2370x over previous
#include <cuda_runtime.h>
#include <cstdint>

// Problem constants
#define T_SEQ 200
#define BATCH 1024
#define EMB   128
#define HID   128
#define G3    384          // 3*HID, gate order r,z,n
#define NROWS (BATCH * T_SEQ)

// 314 MB scratch for gx = x @ W_ih^T + b_ih  (static __device__: allocation-free)
__device__ float g_gx[(size_t)NROWS * G3];

// Packed fp32x2 FMA (gx kernel)
__device__ __forceinline__ void fma2(unsigned long long& d,
                                     unsigned long long a,
                                     unsigned long long b) {
    asm("fma.rn.f32x2 %0, %1, %2, %0;" : "+l"(d) : "l"(a), "l"(b));
}
__device__ __forceinline__ float pairsum(unsigned long long d) {
    float lo = __uint_as_float((unsigned)(d & 0xffffffffULL));
    float hi = __uint_as_float((unsigned)(d >> 32));
    return lo + hi;
}

// ---- bf16 split helpers (RNE via bit trick, matches cvt.rn.bf16) ----
__device__ __forceinline__ unsigned bf16bits(float x) {      // top-16 bits, rounded
    unsigned u = __float_as_uint(x);
    return ((u + 0x7fffu + ((u >> 16) & 1u)) & 0xffff0000u);
}
// split x = hi + lo (both representable in bf16); returns 16-bit patterns
__device__ __forceinline__ void bsplit(float x, unsigned& h16, unsigned& l16) {
    unsigned uh = bf16bits(x);
    float hi = __uint_as_float(uh);
    float lo = x - hi;
    h16 = uh >> 16;
    l16 = bf16bits(lo) >> 16;
}

// D += A*B  (m16n8k16 bf16, fp32 accum)
__device__ __forceinline__ void mma_bf16(float* c,
                                         unsigned a0, unsigned a1, unsigned a2, unsigned a3,
                                         unsigned b0, unsigned b1) {
    asm("mma.sync.aligned.m16n8k16.row.col.f32.bf16.bf16.f32 "
        "{%0,%1,%2,%3}, {%4,%5,%6,%7}, {%8,%9}, {%0,%1,%2,%3};"
        : "+f"(c[0]), "+f"(c[1]), "+f"(c[2]), "+f"(c[3])
        : "r"(a0), "r"(a1), "r"(a2), "r"(a3), "r"(b0), "r"(b1));
}

// ---------------------------------------------------------------------------
// Kernel 1: fused embedding gather + input-side GEMM (R2 version: best known)
// ---------------------------------------------------------------------------
#define RM    64
#define XPAD  132
#define SM1_BYTES ((RM * XPAD + 128 * XPAD) * 4)

__global__ __launch_bounds__(256) void gx_kernel(
    const int*   __restrict__ seq,
    const float* __restrict__ emb,
    const float* __restrict__ Wih,
    const float* __restrict__ bih)
{
    extern __shared__ float sm[];
    float* xs = sm;
    float* ws = sm + RM * XPAD;

    const int t    = threadIdx.x;
    const int row0 = blockIdx.x * RM;
    const int c0   = blockIdx.y * 128;

    {
        int r  = t >> 2;
        int k0 = (t & 3) * 32;
        int idx = __ldg(seq + row0 + r);
        const float4* src = (const float4*)(emb + (size_t)idx * EMB + k0);
        float4* dst = (float4*)(xs + r * XPAD + k0);
        #pragma unroll
        for (int i = 0; i < 8; i++) dst[i] = src[i];
    }
    {
        #pragma unroll
        for (int i = 0; i < 16; i++) {
            int flat = t + 256 * i;
            int c  = flat >> 5;
            int k4 = (flat & 31) << 2;
            *(float4*)(ws + c * XPAD + k4) =
                *(const float4*)(Wih + (size_t)(c0 + c) * EMB + k4);
        }
    }
    __syncthreads();

    const int rg = t >> 5;
    const int cg = t & 31;
    unsigned long long acc[8][4];
    #pragma unroll
    for (int r = 0; r < 8; r++)
        #pragma unroll
        for (int j = 0; j < 4; j++) acc[r][j] = 0ULL;

    const float* xbase = xs + (rg * 8) * XPAD;

    #pragma unroll 4
    for (int k = 0; k < 128; k += 4) {
        ulonglong2 wv[4];
        #pragma unroll
        for (int j = 0; j < 4; j++)
            wv[j] = *(const ulonglong2*)(ws + (cg + 32 * j) * XPAD + k);
        #pragma unroll
        for (int r = 0; r < 8; r++) {
            ulonglong2 xv = *(const ulonglong2*)(xbase + r * XPAD + k);
            #pragma unroll
            for (int j = 0; j < 4; j++) {
                fma2(acc[r][j], xv.x, wv[j].x);
                fma2(acc[r][j], xv.y, wv[j].y);
            }
        }
    }

    #pragma unroll
    for (int j = 0; j < 4; j++) {
        int c = c0 + cg + 32 * j;
        float bv = __ldg(bih + c);
        #pragma unroll
        for (int r = 0; r < 8; r++) {
            int row = row0 + rg * 8 + r;
            g_gx[(size_t)row * G3 + c] = pairsum(acc[r][j]) + bv;
        }
    }
}

// ---------------------------------------------------------------------------
// Kernel 2: GRU recurrence on tensor cores (bf16 2-term split, 3-pass mma).
// CTA = 8 batch rows (padded to M=16), 256 threads = 8 warps.
// Warp w owns gates [48w, 48w+48) = 6 n-tiles; K = 128 = 8 k-tiles.
// W_hh fragments precomputed once into SMEM in per-lane layout (192 KB).
// h lives in phase-2 registers; only packed bf16 hi/lo words go to SMEM.
// ---------------------------------------------------------------------------
#define BM     8
#define GHPAD  388
#define HPITCH 68
// floats: wfrag 49152 + ghs 3104 + hhi/hlo 1088
#define SM2_BYTES ((49152 + BM * GHPAD + 2 * BM * HPITCH) * 4)

__device__ __forceinline__ float fsigmoid(float x) {
    return __fdividef(1.f, 1.f + __expf(-x));
}

__global__ __launch_bounds__(256) void gru_kernel(
    const float* __restrict__ Whh,
    const float* __restrict__ bhh,
    float*       __restrict__ out)
{
    extern __shared__ float sm[];
    uint2*    wfrag = (uint2*)sm;                      // [8w][6i][8j][2s][32l]
    float*    ghs   = sm + 49152;                      // [BM][GHPAD]
    unsigned* hhi   = (unsigned*)(ghs + BM * GHPAD);   // [BM][HPITCH] bf16x2
    unsigned* hlo   = hhi + BM * HPITCH;

    const int t  = threadIdx.x;
    const int w  = t >> 5;
    const int l  = t & 31;
    const int g  = l >> 2;        // mma row / N-index within tile
    const int tg = l & 3;         // mma k/col group
    const int b0 = blockIdx.x * BM;

    // ---- precompute W_hh fragments (once; amortized over 200 steps) ----
    #pragma unroll
    for (int i = 0; i < 6; i++) {
        #pragma unroll
        for (int j = 0; j < 8; j++) {
            int n  = 48 * w + 8 * i + g;
            int kb = 16 * j + 2 * tg;
            const float* Wr = Whh + (size_t)n * HID;
            float w00 = Wr[kb],     w01 = Wr[kb + 1];
            float w08 = Wr[kb + 8], w09 = Wr[kb + 9];
            unsigned h00, l00, h01, l01, h08, l08, h09, l09;
            bsplit(w00, h00, l00);  bsplit(w01, h01, l01);
            bsplit(w08, h08, l08);  bsplit(w09, h09, l09);
            int base = ((w * 6 + i) * 8 + j) * 2;
            wfrag[(base + 0) * 32 + l] = make_uint2(h00 | (h01 << 16), h08 | (h09 << 16));
            wfrag[(base + 1) * 32 + l] = make_uint2(l00 | (l01 << 16), l08 | (l09 << 16));
        }
    }
    // ---- zero h hi/lo words ----
    for (int p = t; p < 2 * BM * HPITCH; p += 256) hhi[p] = 0u;

    // ---- per-warp bias regs (gates 48w+8i+2tg, +1) ----
    float2 bias[6];
    #pragma unroll
    for (int i = 0; i < 6; i++)
        bias[i] = *(const float2*)(bhh + 48 * w + 8 * i + 2 * tg);

    // ---- phase-2 mapping: thread -> k-pair (2k2, 2k2+1) of rows rb, rb+4 ----
    const int k2 = t & 63;
    const int rb = t >> 6;                 // 0..3
    float h0a = 0.f, h0b = 0.f;            // row rb,   k even/odd
    float h1a = 0.f, h1b = 0.f;            // row rb+4, k even/odd
    const size_t gx0 = ((size_t)(b0 + rb)     * T_SEQ) * G3 + 2 * k2;
    const size_t gx1 = ((size_t)(b0 + rb + 4) * T_SEQ) * G3 + 2 * k2;

    const uint2* pw = wfrag + (w * 96) * 32 + l;
    __syncthreads();

    for (int ts = 0; ts < T_SEQ; ts++) {
        // ---- prefetch gx (float2: gates k, k+1 at r/z/n offsets) ----
        const float* gp0 = g_gx + gx0 + (size_t)ts * G3;
        const float* gp1 = g_gx + gx1 + (size_t)ts * G3;
        float2 xr0 = __ldg((const float2*)(gp0));
        float2 xz0 = __ldg((const float2*)(gp0 + 128));
        float2 xn0 = __ldg((const float2*)(gp0 + 256));
        float2 xr1 = __ldg((const float2*)(gp1));
        float2 xz1 = __ldg((const float2*)(gp1 + 128));
        float2 xn1 = __ldg((const float2*)(gp1 + 256));

        // ---- tensor-core GEMM: gh = h @ W_hh^T ----
        float acc[6][4];
        #pragma unroll
        for (int i = 0; i < 6; i++)
            { acc[i][0]=0.f; acc[i][1]=0.f; acc[i][2]=0.f; acc[i][3]=0.f; }

        #pragma unroll
        for (int j = 0; j < 8; j++) {
            unsigned ahi0 = hhi[g * HPITCH + 8 * j + tg];
            unsigned ahi2 = hhi[g * HPITCH + 8 * j + tg + 4];
            unsigned alo0 = hlo[g * HPITCH + 8 * j + tg];
            unsigned alo2 = hlo[g * HPITCH + 8 * j + tg + 4];
            #pragma unroll
            for (int i = 0; i < 6; i++) {
                uint2 bh = pw[((i * 8 + j) * 2 + 0) * 32];
                uint2 bl = pw[((i * 8 + j) * 2 + 1) * 32];
                mma_bf16(acc[i], ahi0, 0u, ahi2, 0u, bh.x, bh.y);  // hi*hi
                mma_bf16(acc[i], ahi0, 0u, ahi2, 0u, bl.x, bl.y);  // hi*lo
                mma_bf16(acc[i], alo0, 0u, alo2, 0u, bh.x, bh.y);  // lo*hi
            }
        }
        // rows 0-7 live in c0,c1 (row g, cols 2tg,2tg+1); add bias, store
        #pragma unroll
        for (int i = 0; i < 6; i++) {
            float2 v = { acc[i][0] + bias[i].x, acc[i][1] + bias[i].y };
            *(float2*)(ghs + g * GHPAD + 48 * w + 8 * i + 2 * tg) = v;
        }
        __syncthreads();

        // ---- phase 2: gates + h update (h stays in registers) ----
        {
            float2 hr = *(const float2*)(ghs + rb * GHPAD + 2 * k2);
            float2 hz = *(const float2*)(ghs + rb * GHPAD + 128 + 2 * k2);
            float2 hn = *(const float2*)(ghs + rb * GHPAD + 256 + 2 * k2);
            float r_a = fsigmoid(xr0.x + hr.x), r_b = fsigmoid(xr0.y + hr.y);
            float z_a = fsigmoid(xz0.x + hz.x), z_b = fsigmoid(xz0.y + hz.y);
            float n_a = 2.f * fsigmoid(2.f * (xn0.x + r_a * hn.x)) - 1.f;
            float n_b = 2.f * fsigmoid(2.f * (xn0.y + r_b * hn.y)) - 1.f;
            h0a = (1.f - z_a) * n_a + z_a * h0a;
            h0b = (1.f - z_b) * n_b + z_b * h0b;
        }
        {
            float2 hr = *(const float2*)(ghs + (rb + 4) * GHPAD + 2 * k2);
            float2 hz = *(const float2*)(ghs + (rb + 4) * GHPAD + 128 + 2 * k2);
            float2 hn = *(const float2*)(ghs + (rb + 4) * GHPAD + 256 + 2 * k2);
            float r_a = fsigmoid(xr1.x + hr.x), r_b = fsigmoid(xr1.y + hr.y);
            float z_a = fsigmoid(xz1.x + hz.x), z_b = fsigmoid(xz1.y + hz.y);
            float n_a = 2.f * fsigmoid(2.f * (xn1.x + r_a * hn.x)) - 1.f;
            float n_b = 2.f * fsigmoid(2.f * (xn1.y + r_b * hn.y)) - 1.f;
            h1a = (1.f - z_a) * n_a + z_a * h1a;
            h1b = (1.f - z_b) * n_b + z_b * h1b;
        }
        // write packed bf16 hi/lo for next step's A fragments
        {
            unsigned ha, la, hb, lb;
            bsplit(h0a, ha, la);  bsplit(h0b, hb, lb);
            hhi[rb * HPITCH + k2] = ha | (hb << 16);
            hlo[rb * HPITCH + k2] = la | (lb << 16);
            bsplit(h1a, ha, la);  bsplit(h1b, hb, lb);
            hhi[(rb + 4) * HPITCH + k2] = ha | (hb << 16);
            hlo[(rb + 4) * HPITCH + k2] = la | (lb << 16);
        }
        __syncthreads();
    }

    // ---- write final hidden state from registers ----
    {
        float2 v0 = { h0a, h0b };
        float2 v1 = { h1a, h1b };
        *(float2*)(out + (size_t)(b0 + rb)     * HID + 2 * k2) = v0;
        *(float2*)(out + (size_t)(b0 + rb + 4) * HID + 2 * k2) = v1;
    }
}

// ---------------------------------------------------------------------------
// Launch
// ---------------------------------------------------------------------------
extern "C" void kernel_launch(void* const* d_in, const int* in_sizes, int n_in,
                              void* d_out, int out_size)
{
    const int*   seq = (const int*)  d_in[0];  // [1024, 200] int32
    const float* emb = (const float*)d_in[1];  // [100000, 128]
    const float* Wih = (const float*)d_in[2];  // [384, 128]
    const float* Whh = (const float*)d_in[3];  // [384, 128]
    const float* bih = (const float*)d_in[4];  // [384]
    const float* bhh = (const float*)d_in[5];  // [384]
    float* out = (float*)d_out;                // [1024, 128]

    cudaFuncSetAttribute(gx_kernel,  cudaFuncAttributeMaxDynamicSharedMemorySize, SM1_BYTES);
    cudaFuncSetAttribute(gru_kernel, cudaFuncAttributeMaxDynamicSharedMemorySize, SM2_BYTES);

    dim3 grid1(NROWS / RM, G3 / 128);          // 3200 x 3
    gx_kernel<<<grid1, 256, SM1_BYTES>>>(seq, emb, Wih, bih);

    gru_kernel<<<BATCH / BM, 256, SM2_BYTES>>>(Whh, bhh, out);
}

// round 8
// speedup vs baseline: 2.5530x; 1.1413x over previous
#include <cuda_runtime.h>
#include <cstdint>

// Problem constants
#define T_SEQ 200
#define BATCH 1024
#define EMB   128
#define HID   128
#define G3    384          // 3*HID, gate order r,z,n
#define NROWS (BATCH * T_SEQ)

// 314 MB scratch for gx = x @ W_ih^T + b_ih  (static __device__: allocation-free)
__device__ float g_gx[(size_t)NROWS * G3];

// ---- bf16 split helpers (RNE via bit trick, matches cvt.rn.bf16) ----
__device__ __forceinline__ unsigned bf16bits(float x) {      // top-16 bits, rounded
    unsigned u = __float_as_uint(x);
    return ((u + 0x7fffu + ((u >> 16) & 1u)) & 0xffff0000u);
}
__device__ __forceinline__ void bsplit(float x, unsigned& h16, unsigned& l16) {
    unsigned uh = bf16bits(x);
    float hi = __uint_as_float(uh);
    float lo = x - hi;
    h16 = uh >> 16;
    l16 = bf16bits(lo) >> 16;
}

// D += A*B  (m16n8k16 bf16, fp32 accum)
__device__ __forceinline__ void mma_bf16(float* c,
                                         unsigned a0, unsigned a1, unsigned a2, unsigned a3,
                                         unsigned b0, unsigned b1) {
    asm("mma.sync.aligned.m16n8k16.row.col.f32.bf16.bf16.f32 "
        "{%0,%1,%2,%3}, {%4,%5,%6,%7}, {%8,%9}, {%0,%1,%2,%3};"
        : "+f"(c[0]), "+f"(c[1]), "+f"(c[2]), "+f"(c[3])
        : "r"(a0), "r"(a1), "r"(a2), "r"(a3), "r"(b0), "r"(b1));
}

// ---------------------------------------------------------------------------
// Kernel 1: fused embedding gather + input GEMM on tensor cores (bf16 3-pass).
// CTA tile 128 rows x 128 cols x K=128; 8 warps, warp tile 32(M) x 64(N).
// hi/lo split done ONCE at staging; hot loop = pure 32-bit LDS + HMMA.
// SMEM tiles pitch 136 ushorts -> fragment word bank = (4g+tg)%32, no conflicts.
// ---------------------------------------------------------------------------
#define MT    128
#define PITCH 136
#define SM1_BYTES (4 * 128 * PITCH * 2)

__global__ __launch_bounds__(256) void gx_kernel(
    const int*   __restrict__ seq,
    const float* __restrict__ emb,
    const float* __restrict__ Wih,
    const float* __restrict__ bih)
{
    extern __shared__ unsigned short smu[];
    unsigned short* xh = smu;                    // [128][PITCH] bf16
    unsigned short* xl = xh + 128 * PITCH;
    unsigned short* wh = xl + 128 * PITCH;
    unsigned short* wl = wh + 128 * PITCH;

    const int t    = threadIdx.x;
    const int row0 = blockIdx.x * MT;
    const int c0   = blockIdx.y * 128;

    // ---- stage x tile (embedding gather) + split: 2 threads/row, 64 floats each
    {
        int r  = t >> 1;
        int k0 = (t & 1) * 64;
        int idx = __ldg(seq + row0 + r);
        const float4* src = (const float4*)(emb + (size_t)idx * EMB + k0);
        #pragma unroll
        for (int i = 0; i < 16; i++) {
            float4 v = src[i];
            unsigned h0,l0,h1,l1,h2,l2,h3,l3;
            bsplit(v.x,h0,l0); bsplit(v.y,h1,l1);
            bsplit(v.z,h2,l2); bsplit(v.w,h3,l3);
            int o = r * PITCH + k0 + 4 * i;
            *(uint2*)(xh + o) = make_uint2(h0 | (h1 << 16), h2 | (h3 << 16));
            *(uint2*)(xl + o) = make_uint2(l0 | (l1 << 16), l2 | (l3 << 16));
        }
    }
    // ---- stage W tile + split
    {
        int c  = t >> 1;
        int k0 = (t & 1) * 64;
        const float4* src = (const float4*)(Wih + (size_t)(c0 + c) * EMB + k0);
        #pragma unroll
        for (int i = 0; i < 16; i++) {
            float4 v = src[i];
            unsigned h0,l0,h1,l1,h2,l2,h3,l3;
            bsplit(v.x,h0,l0); bsplit(v.y,h1,l1);
            bsplit(v.z,h2,l2); bsplit(v.w,h3,l3);
            int o = c * PITCH + k0 + 4 * i;
            *(uint2*)(wh + o) = make_uint2(h0 | (h1 << 16), h2 | (h3 << 16));
            *(uint2*)(wl + o) = make_uint2(l0 | (l1 << 16), l2 | (l3 << 16));
        }
    }
    __syncthreads();

    // ---- warp tiling: 4x2 warps; warp tile M=32 (2 m-subtiles), N=64 (8 n-subtiles)
    const int w     = t >> 5;
    const int lane  = t & 31;
    const int mrow0 = (w & 3) * 32;
    const int ncol0 = (w >> 2) * 64;
    const int g     = lane >> 2;       // 0..7
    const int tg    = lane & 3;        // 0..3

    float acc[2][8][4];
    #pragma unroll
    for (int m = 0; m < 2; m++)
        #pragma unroll
        for (int n = 0; n < 8; n++)
            #pragma unroll
            for (int i = 0; i < 4; i++) acc[m][n][i] = 0.f;

    #pragma unroll
    for (int kt = 0; kt < 8; kt++) {
        const int k0 = kt * 16;
        unsigned ah[2][4], al[2][4];
        #pragma unroll
        for (int m = 0; m < 2; m++) {
            const unsigned short* p = xh + (mrow0 + 16 * m + g) * PITCH + k0 + 2 * tg;
            const unsigned short* q = xl + (mrow0 + 16 * m + g) * PITCH + k0 + 2 * tg;
            ah[m][0] = *(const unsigned*)(p);
            ah[m][1] = *(const unsigned*)(p + 8 * PITCH);
            ah[m][2] = *(const unsigned*)(p + 8);
            ah[m][3] = *(const unsigned*)(p + 8 * PITCH + 8);
            al[m][0] = *(const unsigned*)(q);
            al[m][1] = *(const unsigned*)(q + 8 * PITCH);
            al[m][2] = *(const unsigned*)(q + 8);
            al[m][3] = *(const unsigned*)(q + 8 * PITCH + 8);
        }
        #pragma unroll
        for (int n = 0; n < 8; n++) {
            const unsigned short* p = wh + (ncol0 + 8 * n + g) * PITCH + k0 + 2 * tg;
            const unsigned short* q = wl + (ncol0 + 8 * n + g) * PITCH + k0 + 2 * tg;
            unsigned bh0 = *(const unsigned*)(p);
            unsigned bh1 = *(const unsigned*)(p + 8);
            unsigned bl0 = *(const unsigned*)(q);
            unsigned bl1 = *(const unsigned*)(q + 8);
            #pragma unroll
            for (int m = 0; m < 2; m++) {
                mma_bf16(acc[m][n], ah[m][0], ah[m][1], ah[m][2], ah[m][3], bh0, bh1);
                mma_bf16(acc[m][n], ah[m][0], ah[m][1], ah[m][2], ah[m][3], bl0, bl1);
                mma_bf16(acc[m][n], al[m][0], al[m][1], al[m][2], al[m][3], bh0, bh1);
            }
        }
    }

    // ---- epilogue: + bias, float2 stores to g_gx
    #pragma unroll
    for (int n = 0; n < 8; n++) {
        int col = c0 + ncol0 + n * 8 + 2 * tg;
        float2 bv = *(const float2*)(bih + col);
        #pragma unroll
        for (int m = 0; m < 2; m++) {
            int r0 = row0 + mrow0 + m * 16 + g;
            float2 v0 = { acc[m][n][0] + bv.x, acc[m][n][1] + bv.y };
            float2 v1 = { acc[m][n][2] + bv.x, acc[m][n][3] + bv.y };
            *(float2*)(g_gx + (size_t)r0 * G3 + col)       = v0;
            *(float2*)(g_gx + (size_t)(r0 + 8) * G3 + col) = v1;
        }
    }
}

// ---------------------------------------------------------------------------
// Kernel 2: GRU recurrence on tensor cores (R6 version, verbatim — 490.7 us).
// ---------------------------------------------------------------------------
#define BM     8
#define GHPAD  388
#define HPITCH 68
#define SM2_BYTES ((49152 + BM * GHPAD + 2 * BM * HPITCH) * 4)

__device__ __forceinline__ float fsigmoid(float x) {
    return __fdividef(1.f, 1.f + __expf(-x));
}

__global__ __launch_bounds__(256) void gru_kernel(
    const float* __restrict__ Whh,
    const float* __restrict__ bhh,
    float*       __restrict__ out)
{
    extern __shared__ float sm[];
    uint2*    wfrag = (uint2*)sm;                      // [8w][6i][8j][2s][32l]
    float*    ghs   = sm + 49152;                      // [BM][GHPAD]
    unsigned* hhi   = (unsigned*)(ghs + BM * GHPAD);   // [BM][HPITCH] bf16x2
    unsigned* hlo   = hhi + BM * HPITCH;

    const int t  = threadIdx.x;
    const int w  = t >> 5;
    const int l  = t & 31;
    const int g  = l >> 2;
    const int tg = l & 3;
    const int b0 = blockIdx.x * BM;

    #pragma unroll
    for (int i = 0; i < 6; i++) {
        #pragma unroll
        for (int j = 0; j < 8; j++) {
            int n  = 48 * w + 8 * i + g;
            int kb = 16 * j + 2 * tg;
            const float* Wr = Whh + (size_t)n * HID;
            float w00 = Wr[kb],     w01 = Wr[kb + 1];
            float w08 = Wr[kb + 8], w09 = Wr[kb + 9];
            unsigned h00, l00, h01, l01, h08, l08, h09, l09;
            bsplit(w00, h00, l00);  bsplit(w01, h01, l01);
            bsplit(w08, h08, l08);  bsplit(w09, h09, l09);
            int base = ((w * 6 + i) * 8 + j) * 2;
            wfrag[(base + 0) * 32 + l] = make_uint2(h00 | (h01 << 16), h08 | (h09 << 16));
            wfrag[(base + 1) * 32 + l] = make_uint2(l00 | (l01 << 16), l08 | (l09 << 16));
        }
    }
    for (int p = t; p < 2 * BM * HPITCH; p += 256) hhi[p] = 0u;

    float2 bias[6];
    #pragma unroll
    for (int i = 0; i < 6; i++)
        bias[i] = *(const float2*)(bhh + 48 * w + 8 * i + 2 * tg);

    const int k2 = t & 63;
    const int rb = t >> 6;
    float h0a = 0.f, h0b = 0.f;
    float h1a = 0.f, h1b = 0.f;
    const size_t gx0 = ((size_t)(b0 + rb)     * T_SEQ) * G3 + 2 * k2;
    const size_t gx1 = ((size_t)(b0 + rb + 4) * T_SEQ) * G3 + 2 * k2;

    const uint2* pw = wfrag + (w * 96) * 32 + l;
    __syncthreads();

    for (int ts = 0; ts < T_SEQ; ts++) {
        const float* gp0 = g_gx + gx0 + (size_t)ts * G3;
        const float* gp1 = g_gx + gx1 + (size_t)ts * G3;
        float2 xr0 = __ldg((const float2*)(gp0));
        float2 xz0 = __ldg((const float2*)(gp0 + 128));
        float2 xn0 = __ldg((const float2*)(gp0 + 256));
        float2 xr1 = __ldg((const float2*)(gp1));
        float2 xz1 = __ldg((const float2*)(gp1 + 128));
        float2 xn1 = __ldg((const float2*)(gp1 + 256));

        float acc[6][4];
        #pragma unroll
        for (int i = 0; i < 6; i++)
            { acc[i][0]=0.f; acc[i][1]=0.f; acc[i][2]=0.f; acc[i][3]=0.f; }

        #pragma unroll
        for (int j = 0; j < 8; j++) {
            unsigned ahi0 = hhi[g * HPITCH + 8 * j + tg];
            unsigned ahi2 = hhi[g * HPITCH + 8 * j + tg + 4];
            unsigned alo0 = hlo[g * HPITCH + 8 * j + tg];
            unsigned alo2 = hlo[g * HPITCH + 8 * j + tg + 4];
            #pragma unroll
            for (int i = 0; i < 6; i++) {
                uint2 bh = pw[((i * 8 + j) * 2 + 0) * 32];
                uint2 bl = pw[((i * 8 + j) * 2 + 1) * 32];
                mma_bf16(acc[i], ahi0, 0u, ahi2, 0u, bh.x, bh.y);
                mma_bf16(acc[i], ahi0, 0u, ahi2, 0u, bl.x, bl.y);
                mma_bf16(acc[i], alo0, 0u, alo2, 0u, bh.x, bh.y);
            }
        }
        #pragma unroll
        for (int i = 0; i < 6; i++) {
            float2 v = { acc[i][0] + bias[i].x, acc[i][1] + bias[i].y };
            *(float2*)(ghs + g * GHPAD + 48 * w + 8 * i + 2 * tg) = v;
        }
        __syncthreads();

        {
            float2 hr = *(const float2*)(ghs + rb * GHPAD + 2 * k2);
            float2 hz = *(const float2*)(ghs + rb * GHPAD + 128 + 2 * k2);
            float2 hn = *(const float2*)(ghs + rb * GHPAD + 256 + 2 * k2);
            float r_a = fsigmoid(xr0.x + hr.x), r_b = fsigmoid(xr0.y + hr.y);
            float z_a = fsigmoid(xz0.x + hz.x), z_b = fsigmoid(xz0.y + hz.y);
            float n_a = 2.f * fsigmoid(2.f * (xn0.x + r_a * hn.x)) - 1.f;
            float n_b = 2.f * fsigmoid(2.f * (xn0.y + r_b * hn.y)) - 1.f;
            h0a = (1.f - z_a) * n_a + z_a * h0a;
            h0b = (1.f - z_b) * n_b + z_b * h0b;
        }
        {
            float2 hr = *(const float2*)(ghs + (rb + 4) * GHPAD + 2 * k2);
            float2 hz = *(const float2*)(ghs + (rb + 4) * GHPAD + 128 + 2 * k2);
            float2 hn = *(const float2*)(ghs + (rb + 4) * GHPAD + 256 + 2 * k2);
            float r_a = fsigmoid(xr1.x + hr.x), r_b = fsigmoid(xr1.y + hr.y);
            float z_a = fsigmoid(xz1.x + hz.x), z_b = fsigmoid(xz1.y + hz.y);
            float n_a = 2.f * fsigmoid(2.f * (xn1.x + r_a * hn.x)) - 1.f;
            float n_b = 2.f * fsigmoid(2.f * (xn1.y + r_b * hn.y)) - 1.f;
            h1a = (1.f - z_a) * n_a + z_a * h1a;
            h1b = (1.f - z_b) * n_b + z_b * h1b;
        }
        {
            unsigned ha, la, hb, lb;
            bsplit(h0a, ha, la);  bsplit(h0b, hb, lb);
            hhi[rb * HPITCH + k2] = ha | (hb << 16);
            hlo[rb * HPITCH + k2] = la | (lb << 16);
            bsplit(h1a, ha, la);  bsplit(h1b, hb, lb);
            hhi[(rb + 4) * HPITCH + k2] = ha | (hb << 16);
            hlo[(rb + 4) * HPITCH + k2] = la | (lb << 16);
        }
        __syncthreads();
    }

    {
        float2 v0 = { h0a, h0b };
        float2 v1 = { h1a, h1b };
        *(float2*)(out + (size_t)(b0 + rb)     * HID + 2 * k2) = v0;
        *(float2*)(out + (size_t)(b0 + rb + 4) * HID + 2 * k2) = v1;
    }
}

// ---------------------------------------------------------------------------
// Launch
// ---------------------------------------------------------------------------
extern "C" void kernel_launch(void* const* d_in, const int* in_sizes, int n_in,
                              void* d_out, int out_size)
{
    const int*   seq = (const int*)  d_in[0];  // [1024, 200] int32
    const float* emb = (const float*)d_in[1];  // [100000, 128]
    const float* Wih = (const float*)d_in[2];  // [384, 128]
    const float* Whh = (const float*)d_in[3];  // [384, 128]
    const float* bih = (const float*)d_in[4];  // [384]
    const float* bhh = (const float*)d_in[5];  // [384]
    float* out = (float*)d_out;                // [1024, 128]

    cudaFuncSetAttribute(gx_kernel,  cudaFuncAttributeMaxDynamicSharedMemorySize, SM1_BYTES);
    cudaFuncSetAttribute(gru_kernel, cudaFuncAttributeMaxDynamicSharedMemorySize, SM2_BYTES);

    dim3 grid1(NROWS / MT, G3 / 128);          // 1600 x 3
    gx_kernel<<<grid1, 256, SM1_BYTES>>>(seq, emb, Wih, bih);

    gru_kernel<<<BATCH / BM, 256, SM2_BYTES>>>(Whh, bhh, out);
}